// round 17
// baseline (speedup 1.0000x reference)
#include <cuda_runtime.h>
#include <cuda_fp16.h>
#include <cstdint>

// Problem constants (fixed by setup_inputs)
#define TOKENS 16384
#define DIM    1024
#define CD     16
#define CS     8192

#define N_X  (TOKENS * DIM)
#define N_W  (CD * DIM)
#define N_CB (CS * CD)

// ---- scan tiling ----
#define CHUNK_N   128
#define NCHUNK    (CS / CHUNK_N)      // 64
#define ROWB      112                 // bytes/code row: 56 halves (48 data + 8 pad)
#define SCAN_THREADS 512
#define KB        3                   // fp16 2-split products: hh,hm,mh
#define WSLICE    16
#define WSLICE_B  (WSLICE * ROWB)     // 1792 B
#define WAREA     (2 * WSLICE_B + 2 * 64)

#define OFF_Z    (16 * WAREA)
#define OFF_RES  (OFF_Z + 128 * CD * 4)
#define SCAN_SMEM (OFF_RES + 128 * 8)          // 68608

// proj-in-prologue config
#define P1_QS    4100
#define OFF_W    SCAN_SMEM                     // W: 4 * 4100 floats
#define FUSED_SMEM (SCAN_SMEM + 4 * P1_QS * 4) // 134208 B

// img/bias kernel blocks
#define NB_IMG   (CS * 4 / 256)             // 128
#define NB_PREP  (CS / 256)                 // 32

__device__ float g_hbneg[CS];
__device__ __align__(16) unsigned char g_img[CS * ROWB];

// ---------------- helpers ----------------
__device__ __forceinline__ uint32_t smem_u32(const void* p) {
    uint32_t a;
    asm("{ .reg .u64 t; cvta.to.shared.u64 t, %1; cvt.u32.u64 %0, t; }"
        : "=r"(a) : "l"(p));
    return a;
}
__device__ __forceinline__ void cpa16(uint32_t dst, const void* src) {
    asm volatile("cp.async.ca.shared.global [%0], [%1], 16;"
                 :: "r"(dst), "l"(src) : "memory");
}
__device__ __forceinline__ void cpa_commit() {
    asm volatile("cp.async.commit_group;" ::: "memory");
}
__device__ __forceinline__ void cpa_wait1() {
    asm volatile("cp.async.wait_group 1;" ::: "memory");
}
__device__ __forceinline__ void cpa_wait0() {
    asm volatile("cp.async.wait_group 0;" ::: "memory");
}
__device__ __forceinline__ unsigned int ordf(float f) {
    unsigned int u = __float_as_uint(f);
    return (u & 0x80000000u) ? ~u : (u | 0x80000000u);
}
__device__ __forceinline__ void split2(float f, unsigned short& h, unsigned short& m) {
    __half hh = __float2half_rn(f);
    float fh = __half2float(hh);
    __half mm = __float2half_rn(f - fh);
    h = *reinterpret_cast<unsigned short*>(&hh);
    m = *reinterpret_cast<unsigned short*>(&mm);
}
__device__ __forceinline__ int lvlA(int kb) { return kb >> 1; }
__device__ __forceinline__ int lvlB(int kb) { return kb & 1; }

__device__ __forceinline__ void mma16816(float* d, const uint32_t* a,
                                         uint32_t b0, uint32_t b1) {
    asm volatile(
        "mma.sync.aligned.m16n8k16.row.col.f32.f16.f16.f32 "
        "{%0,%1,%2,%3},{%4,%5,%6,%7},{%8,%9},{%0,%1,%2,%3};"
        : "+f"(d[0]), "+f"(d[1]), "+f"(d[2]), "+f"(d[3])
        : "r"(a[0]), "r"(a[1]), "r"(a[2]), "r"(a[3]), "r"(b0), "r"(b1));
}

// ---------------- kernel A: codebook image + bias ----------------
__global__ void __launch_bounds__(256)
img_prep_kernel(const float* __restrict__ cb) {
    const int b = blockIdx.x;
    const int tid = threadIdx.x;

    if (b < NB_IMG) {
        int idx = b * 256 + tid;
        int k = idx >> 2;
        int t = idx & 3;
        const float* row = cb + (size_t)k * CD;
        float c0 = row[2 * t],     c1 = row[2 * t + 1];
        float c8 = row[2 * t + 8], c9 = row[2 * t + 9];
        unsigned short h0, m0, h1, m1, h8, m8, h9, m9;
        split2(c0, h0, m0); split2(c1, h1, m1);
        split2(c8, h8, m8); split2(c9, h9, m9);
        uint32_t wh0 = (uint32_t)h0 | ((uint32_t)h1 << 16);
        uint32_t wh1 = (uint32_t)h8 | ((uint32_t)h9 << 16);
        uint32_t wm0 = (uint32_t)m0 | ((uint32_t)m1 << 16);
        uint32_t wm1 = (uint32_t)m8 | ((uint32_t)m9 << 16);
        uint32_t* base = reinterpret_cast<uint32_t*>(g_img + (size_t)k * ROWB);
#pragma unroll
        for (int kb = 0; kb < KB; kb++) {
            uint32_t* p = base + kb * 8 + t * 2;
            if (lvlB(kb)) { p[0] = wm0; p[1] = wm1; }
            else          { p[0] = wh0; p[1] = wh1; }
        }
        if (t == 0) {
            uint4 zz = {0u, 0u, 0u, 0u};
            *reinterpret_cast<uint4*>(base + 24) = zz;
        }
    } else {
        int k = (b - NB_IMG) * 256 + tid;
        float s = 0.f;
#pragma unroll
        for (int i = 0; i < CD; i++) {
            float v = cb[(size_t)k * CD + i];
            s = fmaf(v, v, s);
        }
        g_hbneg[k] = -0.5f * s;
    }
}

// ---------------- kernel B: fused proj+LN prologue + mma.sync scan -------------
__global__ void __launch_bounds__(SCAN_THREADS)
scan_fused_kernel(const float* __restrict__ x, const float* __restrict__ W,
                  float* __restrict__ out) {
    extern __shared__ __align__(16) unsigned char sm[];
    const uint32_t sb = smem_u32(sm);

    const int tid  = threadIdx.x;
    const int lane = tid & 31;
    const int w    = tid >> 5;
    const int g    = lane >> 2;
    const int t    = lane & 3;
    const int mi   = w >> 3;
    const int nj   = w & 7;
    const int m_base = mi * 64;
    const int njOff  = nj * WSLICE;
    const int ctaTok = blockIdx.x * 128;
    const uint32_t wbase = sb + w * WAREA;

    unsigned long long* res = reinterpret_cast<unsigned long long*>(sm + OFF_RES);
    if (tid < 128) res[tid] = 0ull;

    // ---- per-warp staging lambda (proven R16 pattern) ----
    auto stage = [&](int ch, int buf) {
        const unsigned char* src = g_img + (size_t)(ch * CHUNK_N + njOff) * ROWB;
        uint32_t dstB = wbase + buf * WSLICE_B;
        cpa16(dstB + lane * 16,        src + lane * 16);
        cpa16(dstB + (lane + 32) * 16, src + (lane + 32) * 16);
        cpa16(dstB + (lane + 64) * 16, src + (lane + 64) * 16);
        if (lane < 16) cpa16(dstB + (lane + 96) * 16, src + (lane + 96) * 16);
        if (lane < 4)
            cpa16(wbase + 2 * WSLICE_B + buf * 64 + lane * 16,
                  g_hbneg + ch * CHUNK_N + njOff + lane * 4);
        cpa_commit();
    };

    // issue first two chunk stages NOW -- they overlap the FMA prologue below
    stage(0, 0);
    stage(1, 1);

    // ================= proj + LN prologue (R16 pattern, 1 token/quad) ==========
    {
        float* wt = reinterpret_cast<float*>(sm + OFF_W);
        const int t4   = tid & 3;
        const int prow = tid >> 2;           // 0..127
        const int token = ctaTok + prow;

        // stage W transposed: wt[dq*QS + dloc*16 + c]
        for (int i = 0; i < N_W / SCAN_THREADS; i++) {
            int idx = tid + i * SCAN_THREADS;
            int c = idx >> 10, d = idx & 1023;
            wt[(d >> 8) * P1_QS + (d & 255) * 16 + c] = W[idx];
        }
        __syncthreads();

        float acc[CD];
#pragma unroll
        for (int c = 0; c < CD; c++) acc[c] = 0.f;

        const float* xr = x + (size_t)token * DIM + t4 * 256;
        const float* wq = wt + t4 * P1_QS;

        for (int db = 0; db < 256; db += 4) {
            float4 xv = *reinterpret_cast<const float4*>(xr + db);
            const float* w0 = wq + (db + 0) * 16;
            const float* w1 = wq + (db + 1) * 16;
            const float* w2 = wq + (db + 2) * 16;
            const float* w3 = wq + (db + 3) * 16;
#pragma unroll
            for (int c = 0; c < CD; c++) {
                acc[c] = fmaf(xv.x, w0[c], acc[c]);
                acc[c] = fmaf(xv.y, w1[c], acc[c]);
                acc[c] = fmaf(xv.z, w2[c], acc[c]);
                acc[c] = fmaf(xv.w, w3[c], acc[c]);
            }
        }

        // combine 4 quarters within the quad
#pragma unroll
        for (int c = 0; c < CD; c++) {
            acc[c] += __shfl_xor_sync(0xffffffffu, acc[c], 1);
            acc[c] += __shfl_xor_sync(0xffffffffu, acc[c], 2);
        }
        if (t4 == 0) {
            float mu = 0.f;
#pragma unroll
            for (int c = 0; c < CD; c++) mu += acc[c];
            mu *= (1.0f / CD);
            float var = 0.f;
#pragma unroll
            for (int c = 0; c < CD; c++) { float d = acc[c] - mu; var = fmaf(d, d, var); }
            var *= (1.0f / CD);
            float inv = rsqrtf(var + 1e-5f);
            float* zs = reinterpret_cast<float*>(sm + OFF_Z) + prow * CD;
#pragma unroll
            for (int c = 0; c < CD; c++) zs[c] = (acc[c] - mu) * inv;
        }
    }
    __syncthreads();

    // ---- register-resident A fragments (from smem z) ----
    uint32_t afr[4][KB][4];
    {
        const float* zb = reinterpret_cast<const float*>(sm + OFF_Z);
        unsigned short sp[2][8][4];
#pragma unroll
        for (int s = 0; s < 8; s++) {
            int row = m_base + g + 8 * s;
#pragma unroll
            for (int jj = 0; jj < 4; jj++) {
                int col = 2 * t + ((jj & 2) ? 8 : 0) + (jj & 1);
                unsigned short h, m;
                split2(zb[row * CD + col], h, m);
                sp[0][s][jj] = h; sp[1][s][jj] = m;
            }
        }
#pragma unroll
        for (int mt = 0; mt < 4; mt++) {
#pragma unroll
            for (int kb = 0; kb < KB; kb++) {
                int lv = lvlA(kb);
                int s0 = 2 * mt, s1 = 2 * mt + 1;
                afr[mt][kb][0] = (uint32_t)sp[lv][s0][0] | ((uint32_t)sp[lv][s0][1] << 16);
                afr[mt][kb][1] = (uint32_t)sp[lv][s1][0] | ((uint32_t)sp[lv][s1][1] << 16);
                afr[mt][kb][2] = (uint32_t)sp[lv][s0][2] | ((uint32_t)sp[lv][s0][3] << 16);
                afr[mt][kb][3] = (uint32_t)sp[lv][s1][2] | ((uint32_t)sp[lv][s1][3] << 16);
            }
        }
    }

    float best[8];
    int   bidx[8];
#pragma unroll
    for (int s = 0; s < 8; s++) { best[s] = -3.0e38f; bidx[s] = 0; }

    for (int ch = 0; ch < NCHUNK; ch++) {
        const int buf = ch & 1;
        if (ch < NCHUNK - 1) cpa_wait1(); else cpa_wait0();
        __syncwarp();

        const uint32_t bB = wbase + buf * WSLICE_B;
        const float* hbs = reinterpret_cast<const float*>(
            sm + (wbase - sb) + 2 * WSLICE_B + buf * 64);
        const int cbase = ch * CHUNK_N + njOff;

#pragma unroll
        for (int nt = 0; nt < 2; nt++) {
            const int lcol = nt * 8 + g;
            const float bx = hbs[nt * 8 + 2 * t];
            const float by = hbs[nt * 8 + 2 * t + 1];
            float d0[4], d1[4], d2[4], d3[4];
#pragma unroll
            for (int mt = 0; mt < 4; mt++) { d0[mt]=bx; d1[mt]=by; d2[mt]=bx; d3[mt]=by; }

#pragma unroll
            for (int kb = 0; kb < KB; kb++) {
                uint32_t b0, b1;
                uint32_t addr = bB + lcol * ROWB + kb * 32 + t * 8;
                asm volatile("ld.shared.v2.u32 {%0,%1}, [%2];"
                             : "=r"(b0), "=r"(b1) : "r"(addr));
#pragma unroll
                for (int mt = 0; mt < 4; mt++) {
                    float dd[4] = {d0[mt], d1[mt], d2[mt], d3[mt]};
                    mma16816(dd, afr[mt][kb], b0, b1);
                    d0[mt]=dd[0]; d1[mt]=dd[1]; d2[mt]=dd[2]; d3[mt]=dd[3];
                }
            }

            const int c0 = cbase + nt * 8 + 2 * t;
#pragma unroll
            for (int mt = 0; mt < 4; mt++) {
                int se = 2 * mt, so = 2 * mt + 1;
                {
                    float pm = fmaxf(d0[mt], d1[mt]);
                    float nb = fmaxf(best[se], pm);
                    if (nb != best[se])
                        bidx[se] = (d1[mt] > d0[mt]) ? c0 + 1 : c0;
                    best[se] = nb;
                }
                {
                    float pm = fmaxf(d2[mt], d3[mt]);
                    float nb = fmaxf(best[so], pm);
                    if (nb != best[so])
                        bidx[so] = (d3[mt] > d2[mt]) ? c0 + 1 : c0;
                    best[so] = nb;
                }
            }
        }

        if (ch + 2 < NCHUNK) stage(ch + 2, buf);
    }

    // ---- combine: quad shfl-reduce, then packed-key max across warps ----
#pragma unroll
    for (int s = 0; s < 8; s++) {
        unsigned int kh = ordf(best[s]);
        unsigned int kl = (unsigned int)(CS - 1 - bidx[s]);
#pragma unroll
        for (int o = 1; o < 4; o <<= 1) {
            unsigned int oh = __shfl_xor_sync(0xffffffffu, kh, o);
            unsigned int ol = __shfl_xor_sync(0xffffffffu, kl, o);
            if (oh > kh || (oh == kh && ol > kl)) { kh = oh; kl = ol; }
        }
        if (t == 0) {
            unsigned long long key = ((unsigned long long)kh << 32) | kl;
            atomicMax(&res[m_base + g + 8 * s], key);
        }
    }
    __syncthreads();

    if (tid < 128) {
        unsigned int low = (unsigned int)(res[tid] & 0xffffffffu);
        out[ctaTok + tid] = (float)(CS - 1 - (int)low);
    }
}

// ---------------- launch ----------------
extern "C" void kernel_launch(void* const* d_in, const int* in_sizes, int n_in,
                              void* d_out, int out_size) {
    const float* x  = nullptr;
    const float* W  = nullptr;
    const float* cb = nullptr;
    for (int i = 0; i < n_in; i++) {
        if      (in_sizes[i] == N_X)      x  = (const float*)d_in[i];
        else if (in_sizes[i] == N_W)      W  = (const float*)d_in[i];
        else if (in_sizes[i] == N_CB)     cb = (const float*)d_in[i];
        else if (in_sizes[i] == 4 * N_X)  x  = (const float*)d_in[i];
        else if (in_sizes[i] == 4 * N_W)  W  = (const float*)d_in[i];
        else if (in_sizes[i] == 4 * N_CB) cb = (const float*)d_in[i];
    }
    if (!x)  x  = (const float*)d_in[0];
    if (!W)  W  = (const float*)d_in[1];
    if (!cb) cb = (const float*)d_in[2];

    float* out = (float*)d_out;

    cudaFuncSetAttribute(scan_fused_kernel,
                         cudaFuncAttributeMaxDynamicSharedMemorySize, FUSED_SMEM);

    img_prep_kernel<<<NB_IMG + NB_PREP, 256>>>(cb);
    scan_fused_kernel<<<TOKENS / 128, SCAN_THREADS, FUSED_SMEM>>>(x, W, out);
}